// round 13
// baseline (speedup 1.0000x reference)
#include <cuda_runtime.h>
#include <cuda_fp16.h>
#include <math.h>
#include <stdint.h>

#define BATCH    8
#define CH       256
#define NHEADS   4
#define HDIM     64
#define NTOK     2304          // 48*48
#define HDTOT    256
#define BN_EPS   1e-5f
#define NQT      (NTOK / 128)  // 18 q-tiles
#define NKVH     18            // KV tiles (of 64) per split half
#define NUNITS   (BATCH * NHEADS * NQT)   // 576

// ---------------- scratch (static device globals; no allocation) ------------
__device__ __align__(16) __half g_xh[BATCH * NTOK * CH];            // [b][n][c]
__device__ __align__(16) __half g_wqkv[384 * CH];                   // [o][c]
__device__ __align__(16) __half g_pwh[CH * HDTOT];                  // [c][o]
__device__ __align__(16) __half g_qh[BATCH * NHEADS * NTOK * HDIM]; // [b][h][n][d]
__device__ __align__(16) __half g_kh[BATCH * NTOK * HDIM];          // [b][n][d]
__device__ __align__(16) __half g_vh[BATCH * NTOK * HDIM];          // [b][n][d]
__device__ __align__(16) __half g_attnh[BATCH * NTOK * HDTOT];      // [b][n][o]
__device__ __align__(16) __half g_yh[BATCH * CH * NTOK];            // [b][c][n] fp16
__device__ __align__(16) float  g_opart[(size_t)NUNITS * 2 * 128 * 64];
__device__ __align__(16) float  g_lpart[NUNITS * 2 * 128];
__device__ int   g_flag[NUNITS];
__device__ float g_sum[CH];
__device__ float g_sumsq[CH];

// ======================= PTX helpers =========================================
__device__ __forceinline__ uint32_t smem_u32(const void* p) {
    uint32_t a;
    asm("{ .reg .u64 t; cvta.to.shared.u64 t, %1; cvt.u32.u64 %0, t; }"
        : "=r"(a) : "l"(p));
    return a;
}

#define MMA16816(c, a, bf)                                              \
    asm volatile("mma.sync.aligned.m16n8k16.row.col.f32.f16.f16.f32 "   \
        "{%0,%1,%2,%3}, {%4,%5,%6,%7}, {%8,%9}, {%0,%1,%2,%3};"         \
        : "+f"((c)[0]), "+f"((c)[1]), "+f"((c)[2]), "+f"((c)[3])        \
        : "r"((a)[0]), "r"((a)[1]), "r"((a)[2]), "r"((a)[3]),           \
          "r"((bf)[0]), "r"((bf)[1]))

#define LDSMX4(d, addr)                                                 \
    asm volatile("ldmatrix.sync.aligned.m8n8.x4.shared.b16 "            \
        "{%0,%1,%2,%3}, [%4];"                                          \
        : "=r"((d)[0]), "=r"((d)[1]), "=r"((d)[2]), "=r"((d)[3])        \
        : "r"(addr))

#define LDSMX4T(d, addr)                                                \
    asm volatile("ldmatrix.sync.aligned.m8n8.x4.trans.shared.b16 "      \
        "{%0,%1,%2,%3}, [%4];"                                          \
        : "=r"((d)[0]), "=r"((d)[1]), "=r"((d)[2]), "=r"((d)[3])        \
        : "r"(addr))

#define CP_ASYNC16(sa, gp)                                              \
    asm volatile("cp.async.ca.shared.global [%0], [%1], 16;"            \
        :: "r"(sa), "l"(gp))
#define CP_COMMIT() asm volatile("cp.async.commit_group;")
#define CP_WAIT0()  asm volatile("cp.async.wait_group 0;")

__device__ __forceinline__ uint32_t packh2(float lo, float hi) {
    uint32_t r;
    asm("cvt.rn.f16x2.f32 %0, %1, %2;" : "=r"(r) : "f"(hi), "f"(lo));
    return r;
}
__device__ __forceinline__ uint32_t ex2h2(uint32_t x) {
    uint32_t r;
    asm("ex2.approx.f16x2 %0, %1;" : "=r"(r) : "r"(x));
    return r;
}
#define SM_SCALE_LOG2E 0.18033688011112042f   // 0.125 * log2(e)
#define ONES_H2 0x3C003C00u                   // half2(1.0, 1.0)

#define GS 72
#define AB (256 * GS * 2)            // A buffer: 256 rows x 64 halves (GS stride)
#define BB (64 * GS * 2)             // B buffer: 64 rows
#define GEMM_SMEM (2 * (AB + BB))    // 92160 bytes

extern __shared__ __align__(16) uint8_t dynsm[];

// ---- K0: transpose+convert x [b][c][n]->[b][n][c] f16, + weight conv --------
__global__ __launch_bounds__(256) void prep_kernel(const float* __restrict__ x,
                                                   const float* __restrict__ qw,
                                                   const float* __restrict__ kw,
                                                   const float* __restrict__ vw,
                                                   const float* __restrict__ pw) {
    __shared__ float t[32][33];
    const int flat = (blockIdx.z * 8 + blockIdx.y) * 72 + blockIdx.x;
    if (flat == 0) { g_sum[threadIdx.x] = 0.f; g_sumsq[threadIdx.x] = 0.f; }
    if (flat < 640) {
        int idx = flat * 256 + threadIdx.x;    // < 163840
        if (idx < 384 * CH) {
            int o = idx >> 8, c = idx & 255;
            float v;
            if (o < 256)      v = qw[o * CH + c];
            else if (o < 320) v = kw[(o - 256) * CH + c];
            else              v = vw[(o - 320) * CH + c];
            g_wqkv[idx] = __float2half(v);
        } else {
            int j = idx - 384 * CH;            // < 256*256
            g_pwh[j] = __float2half(pw[j]);
        }
    } else if (flat < 643) {
        int idx = (flat - 640) * 256 + threadIdx.x;
        if (idx < NUNITS) g_flag[idx] = 0;
    }

    const int n0 = blockIdx.x * 32;
    const int c0 = blockIdx.y * 32;
    const int b  = blockIdx.z;
    const int tx = threadIdx.x & 31, ty = threadIdx.x >> 5;
#pragma unroll
    for (int i = 0; i < 4; i++) {
        int cl = ty + i * 8;
        t[cl][tx] = x[((size_t)b * CH + c0 + cl) * NTOK + n0 + tx];
    }
    __syncthreads();
#pragma unroll
    for (int p = 0; p < 2; p++) {
        int w = threadIdx.x + p * 256;       // 512 items
        int nl = w >> 4, cp = w & 15;
        __half2 h = __floats2half2_rn(t[2 * cp][nl], t[2 * cp + 1][nl]);
        *(__half2*)&g_xh[((size_t)b * NTOK + n0 + nl) * CH + c0 + 2 * cp] = h;
    }
}

// ---------------- K1: QKV projection via HMMA, wide tile ---------------------
__global__ __launch_bounds__(256) void qkv_kernel() {
    const int bx = blockIdx.x, by = blockIdx.y, b = blockIdx.z;
    const int tid = threadIdx.x;
    const int w = tid >> 5, l = tid & 31;
    const int lr = l >> 2, c2 = (l & 3) * 2, t = l >> 3, rr = l & 7;
    const int q8 = tid & 7;

    const __half* Ag = g_xh + ((size_t)b * NTOK + bx * 256) * CH;
    const __half* Bg = g_wqkv + (size_t)by * 64 * CH;

    const uint32_t sm = smem_u32(dynsm);
    const uint32_t ldA0 = (uint32_t)((w * 32 + (t & 1) * 8 + rr) * GS + (t >> 1) * 8) * 2;
    const uint32_t ldB0 = (uint32_t)(((t >> 1) * 8 + rr) * GS + (t & 1) * 8) * 2;

    float acc[2][8][4];
#pragma unroll
    for (int mi = 0; mi < 2; mi++)
#pragma unroll
        for (int nb = 0; nb < 8; nb++)
#pragma unroll
            for (int i = 0; i < 4; i++) acc[mi][nb][i] = 0.f;

#pragma unroll
    for (int p = 0; p < 8; p++) {
        int row = (tid + p * 256) >> 3;
        CP_ASYNC16(sm + (uint32_t)(row * GS + q8 * 8) * 2,
                   Ag + (size_t)row * CH + q8 * 8);
    }
#pragma unroll
    for (int p = 0; p < 2; p++) {
        int row = (tid + p * 256) >> 3;
        CP_ASYNC16(sm + 2 * AB + (uint32_t)(row * GS + q8 * 8) * 2,
                   Bg + (size_t)row * CH + q8 * 8);
    }
    CP_COMMIT(); CP_WAIT0(); __syncthreads();

    for (int ck = 0; ck < 4; ck++) {
        const uint32_t abase = sm + (uint32_t)(ck & 1) * AB;
        const uint32_t bbase = sm + 2 * AB + (uint32_t)(ck & 1) * BB;
        if (ck < 3) {
            const int co = (ck + 1) * 64;
            const uint32_t a2 = sm + (uint32_t)((ck + 1) & 1) * AB;
            const uint32_t b2 = sm + 2 * AB + (uint32_t)((ck + 1) & 1) * BB;
#pragma unroll
            for (int p = 0; p < 8; p++) {
                int row = (tid + p * 256) >> 3;
                CP_ASYNC16(a2 + (uint32_t)(row * GS + q8 * 8) * 2,
                           Ag + (size_t)row * CH + co + q8 * 8);
            }
#pragma unroll
            for (int p = 0; p < 2; p++) {
                int row = (tid + p * 256) >> 3;
                CP_ASYNC16(b2 + (uint32_t)(row * GS + q8 * 8) * 2,
                           Bg + (size_t)row * CH + co + q8 * 8);
            }
            CP_COMMIT();
        }
#pragma unroll
        for (int ks = 0; ks < 4; ks++) {
            uint32_t aq0[4], aq1[4];
            LDSMX4(aq0, abase + ldA0 + (uint32_t)(ks * 16) * 2);
            LDSMX4(aq1, abase + ldA0 + (uint32_t)(16 * GS + ks * 16) * 2);
#pragma unroll
            for (int nbp = 0; nbp < 4; nbp++) {
                uint32_t bk[4];
                LDSMX4(bk, bbase + ldB0 + (uint32_t)(nbp * 16 * GS + ks * 16) * 2);
                MMA16816(acc[0][2 * nbp],     aq0, (&bk[0]));
                MMA16816(acc[0][2 * nbp + 1], aq0, (&bk[2]));
                MMA16816(acc[1][2 * nbp],     aq1, (&bk[0]));
                MMA16816(acc[1][2 * nbp + 1], aq1, (&bk[2]));
            }
        }
        if (ck < 3) CP_WAIT0();
        __syncthreads();
    }

    __half* base;
    float osc = 1.f;
    if (by < 4)       { base = g_qh + (size_t)(b * NHEADS + by) * NTOK * HDIM;
                        osc = SM_SCALE_LOG2E; }
    else if (by == 4)   base = g_kh + (size_t)b * NTOK * HDIM;
    else                base = g_vh + (size_t)b * NTOK * HDIM;
#pragma unroll
    for (int mi = 0; mi < 2; mi++) {
        const int n_r0 = bx * 256 + w * 32 + mi * 16 + lr;
#pragma unroll
        for (int nb = 0; nb < 8; nb++) {
            int col = nb * 8 + c2;
            *(__half2*)&base[(size_t)n_r0 * HDIM + col] =
                __floats2half2_rn(acc[mi][nb][0] * osc, acc[mi][nb][1] * osc);
            *(__half2*)&base[(size_t)(n_r0 + 8) * HDIM + col] =
                __floats2half2_rn(acc[mi][nb][2] * osc, acc[mi][nb][3] * osc);
        }
    }
}

// ---------------- K2: flash attention via HMMA, split-KV x2 ------------------
// grid (36, 4, 8): blockIdx.x = qt*2 + half. Each CTA does 18 KV tiles.
// Partials (unnormalized O fp32 + row sums) combined by the 2nd-arriving CTA.
#define KVS 72
__global__ __launch_bounds__(128)
void attn_kernel() {
    __shared__ __half smK[2][64 * KVS];
    __shared__ __half smV[2][64 * KVS];
    __shared__ int s_old;

    const int qt   = blockIdx.x >> 1;
    const int half = blockIdx.x & 1;
    const int n0  = qt * 128;
    const int h   = blockIdx.y;
    const int b   = blockIdx.z;
    const int tid = threadIdx.x;
    const int w   = tid >> 5;
    const int l   = tid & 31;
    const int row0 = w * 32;

    const int lr  = l >> 2;
    const int c2  = (l & 3) * 2;
    const int t   = l >> 3;
    const int rr  = l & 7;

    const __half* qg = g_qh + ((size_t)(b * NHEADS + h) * NTOK + n0 + row0) * HDIM;
    uint32_t aq[2][4][4];
#pragma unroll
    for (int mi = 0; mi < 2; mi++)
#pragma unroll
        for (int ks = 0; ks < 4; ks++) {
            aq[mi][ks][0] = *(const uint32_t*)&qg[(mi * 16 + lr)     * HDIM + ks * 16 + c2];
            aq[mi][ks][1] = *(const uint32_t*)&qg[(mi * 16 + lr + 8) * HDIM + ks * 16 + c2];
            aq[mi][ks][2] = *(const uint32_t*)&qg[(mi * 16 + lr)     * HDIM + ks * 16 + c2 + 8];
            aq[mi][ks][3] = *(const uint32_t*)&qg[(mi * 16 + lr + 8) * HDIM + ks * 16 + c2 + 8];
        }

    const uint32_t smK_a = smem_u32(smK);
    const uint32_t smV_a = smem_u32(smV);
    const uint32_t bufB = (uint32_t)(64 * KVS * 2);
    const uint32_t ldK0 = smK_a + (uint32_t)(((t >> 1) * 8 + rr) * KVS + (t & 1) * 8) * 2;
    const uint32_t ldV0 = smV_a + (uint32_t)(((t & 1) * 8 + rr) * KVS + (t >> 1) * 8) * 2;

    const int q0 = tid & 7;
    const __half* kg = g_kh + ((size_t)b * NTOK + half * (NKVH * 64)) * HDIM;
    const __half* vg = g_vh + ((size_t)b * NTOK + half * (NKVH * 64)) * HDIM;

    float oacc[2][8][4];
#pragma unroll
    for (int mi = 0; mi < 2; mi++)
#pragma unroll
        for (int nb = 0; nb < 8; nb++)
#pragma unroll
            for (int i = 0; i < 4; i++) oacc[mi][nb][i] = 0.f;
    float lacc[2][4] = {{0.f, 0.f, 0.f, 0.f}, {0.f, 0.f, 0.f, 0.f}};
    const uint32_t ones[2] = {ONES_H2, ONES_H2};

#pragma unroll
    for (int p = 0; p < 4; p++) {
        int rl = (tid + p * 128) >> 3;
        uint32_t so = (uint32_t)(rl * KVS + q0 * 8) * 2;
        CP_ASYNC16(smK_a + so, kg + (size_t)rl * HDIM + q0 * 8);
        CP_ASYNC16(smV_a + so, vg + (size_t)rl * HDIM + q0 * 8);
    }
    CP_COMMIT();
    CP_WAIT0();
    __syncthreads();

    for (int it = 0; it < NKVH; it++) {
        const uint32_t boff = (uint32_t)(it & 1) * bufB;

        if (it + 1 < NKVH) {
            const int m1 = (it + 1) * 64;
            const uint32_t nb2 = (uint32_t)((it + 1) & 1) * bufB;
#pragma unroll
            for (int p = 0; p < 4; p++) {
                int rl = (tid + p * 128) >> 3;
                uint32_t so = nb2 + (uint32_t)(rl * KVS + q0 * 8) * 2;
                CP_ASYNC16(smK_a + so, kg + (size_t)(m1 + rl) * HDIM + q0 * 8);
                CP_ASYNC16(smV_a + so, vg + (size_t)(m1 + rl) * HDIM + q0 * 8);
            }
            CP_COMMIT();
        }

        uint32_t ap0[2][2][4], ap1[2][2][4];

        // ===== half A: j in [0,32) ===========================================
        {
            float sacc[2][4][4];
#pragma unroll
            for (int mi = 0; mi < 2; mi++)
#pragma unroll
                for (int nb = 0; nb < 4; nb++)
#pragma unroll
                    for (int i = 0; i < 4; i++) sacc[mi][nb][i] = 0.f;
#pragma unroll
            for (int ks = 0; ks < 4; ks++) {
                uint32_t bk0[4], bk1[4];
                LDSMX4(bk0, ldK0 + boff + (uint32_t)(0 * 16 * KVS + ks * 16) * 2);
                LDSMX4(bk1, ldK0 + boff + (uint32_t)(1 * 16 * KVS + ks * 16) * 2);
#pragma unroll
                for (int mi = 0; mi < 2; mi++) {
                    MMA16816(sacc[mi][0], aq[mi][ks], (&bk0[0]));
                    MMA16816(sacc[mi][1], aq[mi][ks], (&bk0[2]));
                    MMA16816(sacc[mi][2], aq[mi][ks], (&bk1[0]));
                    MMA16816(sacc[mi][3], aq[mi][ks], (&bk1[2]));
                }
            }
#pragma unroll
            for (int mi = 0; mi < 2; mi++)
#pragma unroll
                for (int kh = 0; kh < 2; kh++) {
                    ap0[mi][kh][0] = ex2h2(packh2(sacc[mi][2 * kh][0],     sacc[mi][2 * kh][1]));
                    ap0[mi][kh][1] = ex2h2(packh2(sacc[mi][2 * kh][2],     sacc[mi][2 * kh][3]));
                    ap0[mi][kh][2] = ex2h2(packh2(sacc[mi][2 * kh + 1][0], sacc[mi][2 * kh + 1][1]));
                    ap0[mi][kh][3] = ex2h2(packh2(sacc[mi][2 * kh + 1][2], sacc[mi][2 * kh + 1][3]));
                }
        }

        // ===== half B MMA1: j in [32,64) =====================================
        {
            float sacc[2][4][4];
#pragma unroll
            for (int mi = 0; mi < 2; mi++)
#pragma unroll
                for (int nb = 0; nb < 4; nb++)
#pragma unroll
                    for (int i = 0; i < 4; i++) sacc[mi][nb][i] = 0.f;
#pragma unroll
            for (int ks = 0; ks < 4; ks++) {
                uint32_t bk0[4], bk1[4];
                LDSMX4(bk0, ldK0 + boff + (uint32_t)(2 * 16 * KVS + ks * 16) * 2);
                LDSMX4(bk1, ldK0 + boff + (uint32_t)(3 * 16 * KVS + ks * 16) * 2);
#pragma unroll
                for (int mi = 0; mi < 2; mi++) {
                    MMA16816(sacc[mi][0], aq[mi][ks], (&bk0[0]));
                    MMA16816(sacc[mi][1], aq[mi][ks], (&bk0[2]));
                    MMA16816(sacc[mi][2], aq[mi][ks], (&bk1[0]));
                    MMA16816(sacc[mi][3], aq[mi][ks], (&bk1[2]));
                }
            }

#pragma unroll
            for (int kh = 0; kh < 2; kh++) {
                uint32_t bv[4][4];
#pragma unroll
                for (int nbp = 0; nbp < 4; nbp++)
                    LDSMX4T(bv[nbp], ldV0 + boff + (uint32_t)(kh * 16 * KVS + nbp * 16) * 2);
#pragma unroll
                for (int mi = 0; mi < 2; mi++) {
                    MMA16816(lacc[mi], ap0[mi][kh], ones);
#pragma unroll
                    for (int nbp = 0; nbp < 4; nbp++) {
                        MMA16816(oacc[mi][2 * nbp],     ap0[mi][kh], (&bv[nbp][0]));
                        MMA16816(oacc[mi][2 * nbp + 1], ap0[mi][kh], (&bv[nbp][2]));
                    }
                }
            }

#pragma unroll
            for (int mi = 0; mi < 2; mi++)
#pragma unroll
                for (int kh = 0; kh < 2; kh++) {
                    ap1[mi][kh][0] = ex2h2(packh2(sacc[mi][2 * kh][0],     sacc[mi][2 * kh][1]));
                    ap1[mi][kh][1] = ex2h2(packh2(sacc[mi][2 * kh][2],     sacc[mi][2 * kh][3]));
                    ap1[mi][kh][2] = ex2h2(packh2(sacc[mi][2 * kh + 1][0], sacc[mi][2 * kh + 1][1]));
                    ap1[mi][kh][3] = ex2h2(packh2(sacc[mi][2 * kh + 1][2], sacc[mi][2 * kh + 1][3]));
                }
        }

#pragma unroll
        for (int kh = 0; kh < 2; kh++) {
            uint32_t bv[4][4];
#pragma unroll
            for (int nbp = 0; nbp < 4; nbp++)
                LDSMX4T(bv[nbp], ldV0 + boff + (uint32_t)((kh + 2) * 16 * KVS + nbp * 16) * 2);
#pragma unroll
            for (int mi = 0; mi < 2; mi++) {
                MMA16816(lacc[mi], ap1[mi][kh], ones);
#pragma unroll
                for (int nbp = 0; nbp < 4; nbp++) {
                    MMA16816(oacc[mi][2 * nbp],     ap1[mi][kh], (&bv[nbp][0]));
                    MMA16816(oacc[mi][2 * nbp + 1], ap1[mi][kh], (&bv[nbp][2]));
                }
            }
        }

        if (it + 1 < NKVH) CP_WAIT0();
        __syncthreads();
    }

    // ---- store own partial (unnormalized O + row sums) ----------------------
    const int unit = (b * NHEADS + h) * NQT + qt;
    float* op  = g_opart + ((size_t)unit * 2 + half) * (128 * 64);
    float* lpp = g_lpart + ((size_t)unit * 2 + half) * 128;
#pragma unroll
    for (int mi = 0; mi < 2; mi++) {
        int r0 = row0 + mi * 16 + lr;
#pragma unroll
        for (int nb = 0; nb < 8; nb++) {
            int col = nb * 8 + c2;
            *(float2*)&op[(size_t)r0 * 64 + col] =
                make_float2(oacc[mi][nb][0], oacc[mi][nb][1]);
            *(float2*)&op[(size_t)(r0 + 8) * 64 + col] =
                make_float2(oacc[mi][nb][2], oacc[mi][nb][3]);
        }
        if ((l & 3) == 0) { lpp[r0] = lacc[mi][0]; lpp[r0 + 8] = lacc[mi][2]; }
    }
    __threadfence();
    __syncthreads();
    if (tid == 0) s_old = atomicAdd(&g_flag[unit], 1);
    __syncthreads();
    if (s_old == 0) return;      // first arriver: partner will combine
    __threadfence();

    // ---- combine: own regs + partner partial, normalize, write half --------
    const float* oo = g_opart + ((size_t)unit * 2 + (half ^ 1)) * (128 * 64);
    const float* lo = g_lpart + ((size_t)unit * 2 + (half ^ 1)) * 128;
    __half* ob = g_attnh + ((size_t)b * NTOK + n0 + row0) * HDTOT + h * HDIM;
#pragma unroll
    for (int mi = 0; mi < 2; mi++) {
        int r0 = row0 + mi * 16 + lr;
        float inv0 = 1.f / (lacc[mi][0] + lo[r0]);
        float inv1 = 1.f / (lacc[mi][2] + lo[r0 + 8]);
#pragma unroll
        for (int nb = 0; nb < 8; nb++) {
            int col = nb * 8 + c2;
            float2 a0 = *(const float2*)&oo[(size_t)r0 * 64 + col];
            float2 a1 = *(const float2*)&oo[(size_t)(r0 + 8) * 64 + col];
            *(__half2*)&ob[(size_t)(mi * 16 + lr) * HDTOT + col] =
                __floats2half2_rn((oacc[mi][nb][0] + a0.x) * inv0,
                                  (oacc[mi][nb][1] + a0.y) * inv0);
            *(__half2*)&ob[(size_t)(mi * 16 + lr + 8) * HDTOT + col] =
                __floats2half2_rn((oacc[mi][nb][2] + a1.x) * inv1,
                                  (oacc[mi][nb][3] + a1.y) * inv1);
        }
    }
}

// ---------------- K3: output projection via HMMA, wide tile -----------------
__global__ __launch_bounds__(256) void proj_kernel(const float* __restrict__ pb) {
    const int bx = blockIdx.x, b = blockIdx.z;
    const int tid = threadIdx.x;
    const int w = tid >> 5, l = tid & 31;
    const int lr = l >> 2, c2 = (l & 3) * 2, t = l >> 3, rr = l & 7;
    const int q8 = tid & 7;

    const __half* Ag = g_pwh;
    const __half* Bg = g_attnh + ((size_t)b * NTOK + bx * 64) * HDTOT;

    const uint32_t sm = smem_u32(dynsm);
    const uint32_t ldA0 = (uint32_t)((w * 32 + (t & 1) * 8 + rr) * GS + (t >> 1) * 8) * 2;
    const uint32_t ldB0 = (uint32_t)(((t >> 1) * 8 + rr) * GS + (t & 1) * 8) * 2;

    float acc[2][8][4];
#pragma unroll
    for (int mi = 0; mi < 2; mi++)
#pragma unroll
        for (int nb = 0; nb < 8; nb++)
#pragma unroll
            for (int i = 0; i < 4; i++) acc[mi][nb][i] = 0.f;

#pragma unroll
    for (int p = 0; p < 8; p++) {
        int row = (tid + p * 256) >> 3;
        CP_ASYNC16(sm + (uint32_t)(row * GS + q8 * 8) * 2,
                   Ag + (size_t)row * HDTOT + q8 * 8);
    }
#pragma unroll
    for (int p = 0; p < 2; p++) {
        int row = (tid + p * 256) >> 3;
        CP_ASYNC16(sm + 2 * AB + (uint32_t)(row * GS + q8 * 8) * 2,
                   Bg + (size_t)row * HDTOT + q8 * 8);
    }
    CP_COMMIT(); CP_WAIT0(); __syncthreads();

    for (int ck = 0; ck < 4; ck++) {
        const uint32_t abase = sm + (uint32_t)(ck & 1) * AB;
        const uint32_t bbase = sm + 2 * AB + (uint32_t)(ck & 1) * BB;
        if (ck < 3) {
            const int co = (ck + 1) * 64;
            const uint32_t a2 = sm + (uint32_t)((ck + 1) & 1) * AB;
            const uint32_t b2 = sm + 2 * AB + (uint32_t)((ck + 1) & 1) * BB;
#pragma unroll
            for (int p = 0; p < 8; p++) {
                int row = (tid + p * 256) >> 3;
                CP_ASYNC16(a2 + (uint32_t)(row * GS + q8 * 8) * 2,
                           Ag + (size_t)row * HDTOT + co + q8 * 8);
            }
#pragma unroll
            for (int p = 0; p < 2; p++) {
                int row = (tid + p * 256) >> 3;
                CP_ASYNC16(b2 + (uint32_t)(row * GS + q8 * 8) * 2,
                           Bg + (size_t)row * HDTOT + co + q8 * 8);
            }
            CP_COMMIT();
        }
#pragma unroll
        for (int ks = 0; ks < 4; ks++) {
            uint32_t aq0[4], aq1[4];
            LDSMX4(aq0, abase + ldA0 + (uint32_t)(ks * 16) * 2);
            LDSMX4(aq1, abase + ldA0 + (uint32_t)(16 * GS + ks * 16) * 2);
#pragma unroll
            for (int nbp = 0; nbp < 4; nbp++) {
                uint32_t bk[4];
                LDSMX4(bk, bbase + ldB0 + (uint32_t)(nbp * 16 * GS + ks * 16) * 2);
                MMA16816(acc[0][2 * nbp],     aq0, (&bk[0]));
                MMA16816(acc[0][2 * nbp + 1], aq0, (&bk[2]));
                MMA16816(acc[1][2 * nbp],     aq1, (&bk[0]));
                MMA16816(acc[1][2 * nbp + 1], aq1, (&bk[2]));
            }
        }
        if (ck < 3) CP_WAIT0();
        __syncthreads();
    }

    const int n0 = bx * 64;
#pragma unroll
    for (int mi = 0; mi < 2; mi++) {
        const int c_r0 = w * 32 + mi * 16 + lr;
        const int c_r1 = c_r0 + 8;
        const float b0 = pb[c_r0], b1 = pb[c_r1];
        float s0 = 0.f, q0s = 0.f, s1 = 0.f, q1s = 0.f;
#pragma unroll
        for (int nb = 0; nb < 8; nb++) {
            int col = n0 + nb * 8 + c2;
            float v0 = acc[mi][nb][0] + b0, v1 = acc[mi][nb][1] + b0;
            float v2 = acc[mi][nb][2] + b1, v3 = acc[mi][nb][3] + b1;
            *(__half2*)&g_yh[((size_t)b * CH + c_r0) * NTOK + col] =
                __floats2half2_rn(v0, v1);
            *(__half2*)&g_yh[((size_t)b * CH + c_r1) * NTOK + col] =
                __floats2half2_rn(v2, v3);
            s0 += v0 + v1; q0s += v0 * v0 + v1 * v1;
            s1 += v2 + v3; q1s += v2 * v2 + v3 * v3;
        }
        s0 += __shfl_xor_sync(0xffffffffu, s0, 1);  s0 += __shfl_xor_sync(0xffffffffu, s0, 2);
        q0s += __shfl_xor_sync(0xffffffffu, q0s, 1); q0s += __shfl_xor_sync(0xffffffffu, q0s, 2);
        s1 += __shfl_xor_sync(0xffffffffu, s1, 1);  s1 += __shfl_xor_sync(0xffffffffu, s1, 2);
        q1s += __shfl_xor_sync(0xffffffffu, q1s, 1); q1s += __shfl_xor_sync(0xffffffffu, q1s, 2);
        if ((l & 3) == 0) {
            atomicAdd(&g_sum[c_r0], s0);  atomicAdd(&g_sumsq[c_r0], q0s);
            atomicAdd(&g_sum[c_r1], s1);  atomicAdd(&g_sumsq[c_r1], q1s);
        }
    }
}

// ---------------- K4: BN finalize + residual (y in fp16) ---------------------
__global__ __launch_bounds__(192) void bn_kernel(const float* __restrict__ x,
                                                 const float* __restrict__ gamma,
                                                 const float* __restrict__ beta,
                                                 float* __restrict__ out) {
    const int i = blockIdx.x * 192 + threadIdx.x;   // float4 index; grid.x = 3
    const int c = blockIdx.y;
    const int b = blockIdx.z;
    const float invcnt = 1.f / (float)(BATCH * NTOK);
    float mean = g_sum[c] * invcnt;
    float var  = g_sumsq[c] * invcnt - mean * mean;
    float a = gamma[c] * rsqrtf(var + BN_EPS);
    float sh = beta[c] - a * mean;
    size_t i4 = (((size_t)b * CH + c) * NTOK) / 4 + i;
    __half2 y01 = ((const __half2*)g_yh)[i4 * 2];
    __half2 y23 = ((const __half2*)g_yh)[i4 * 2 + 1];
    float4 xr = ((const float4*)x)[i4];
    float2 f01 = __half22float2(y01);
    float2 f23 = __half22float2(y23);
    ((float4*)out)[i4] = make_float4(a * f01.x + sh + xr.x, a * f01.y + sh + xr.y,
                                     a * f23.x + sh + xr.z, a * f23.y + sh + xr.w);
}

// ---------------- launch ------------------------------------------------------
extern "C" void kernel_launch(void* const* d_in, const int* in_sizes, int n_in,
                              void* d_out, int out_size) {
    const float* x     = (const float*)d_in[0];
    const float* qw    = (const float*)d_in[1];
    const float* kw    = (const float*)d_in[2];
    const float* vw    = (const float*)d_in[3];
    const float* pw    = (const float*)d_in[4];
    const float* pb    = (const float*)d_in[5];
    const float* gamma = (const float*)d_in[6];
    const float* beta  = (const float*)d_in[7];
    float* out = (float*)d_out;

    cudaFuncSetAttribute(qkv_kernel, cudaFuncAttributeMaxDynamicSharedMemorySize,
                         GEMM_SMEM);
    cudaFuncSetAttribute(proj_kernel, cudaFuncAttributeMaxDynamicSharedMemorySize,
                         GEMM_SMEM);

    prep_kernel<<<dim3(NTOK / 32, CH / 32, BATCH), 256>>>(x, qw, kw, vw, pw);
    qkv_kernel<<<dim3(NTOK / 256, 6, BATCH), 256, GEMM_SMEM>>>();
    attn_kernel<<<dim3(NQT * 2, NHEADS, BATCH), 128>>>();
    proj_kernel<<<dim3(NTOK / 64, 1, BATCH), 256, GEMM_SMEM>>>(pb);
    bn_kernel<<<dim3(NTOK / 768, CH, BATCH), 192>>>(x, gamma, beta, out);
}

// round 14
// speedup vs baseline: 1.0454x; 1.0454x over previous
#include <cuda_runtime.h>
#include <cuda_fp16.h>
#include <math.h>
#include <stdint.h>

#define BATCH    8
#define CH       256
#define NHEADS   4
#define HDIM     64
#define NTOK     2304          // 48*48
#define HDTOT    256
#define BN_EPS   1e-5f
#define NKV      (NTOK / 64)   // 36

// ---------------- scratch (static device globals; no allocation) ------------
__device__ __align__(16) __half g_xh[BATCH * NTOK * CH];            // [b][n][c]
__device__ __align__(16) __half g_wqkv[384 * CH];                   // [o][c]
__device__ __align__(16) __half g_pwh[CH * HDTOT];                  // [c][o]
__device__ __align__(16) __half g_qh[BATCH * NHEADS * NTOK * HDIM]; // [b][h][n][d]
__device__ __align__(16) __half g_kh[BATCH * NTOK * HDIM];          // [b][n][d]
__device__ __align__(16) __half g_vh[BATCH * NTOK * HDIM];          // [b][n][d]
__device__ __align__(16) __half g_attnh[BATCH * NTOK * HDTOT];      // [b][n][o]
__device__ __align__(16) __half g_yh[BATCH * CH * NTOK];            // [b][c][n] fp16
__device__ float g_sum[CH];
__device__ float g_sumsq[CH];

// ======================= PTX helpers =========================================
__device__ __forceinline__ uint32_t smem_u32(const void* p) {
    uint32_t a;
    asm("{ .reg .u64 t; cvta.to.shared.u64 t, %1; cvt.u32.u64 %0, t; }"
        : "=r"(a) : "l"(p));
    return a;
}

#define MMA16816(c, a, bf)                                              \
    asm volatile("mma.sync.aligned.m16n8k16.row.col.f32.f16.f16.f32 "   \
        "{%0,%1,%2,%3}, {%4,%5,%6,%7}, {%8,%9}, {%0,%1,%2,%3};"         \
        : "+f"((c)[0]), "+f"((c)[1]), "+f"((c)[2]), "+f"((c)[3])        \
        : "r"((a)[0]), "r"((a)[1]), "r"((a)[2]), "r"((a)[3]),           \
          "r"((bf)[0]), "r"((bf)[1]))

#define LDSMX4(d, addr)                                                 \
    asm volatile("ldmatrix.sync.aligned.m8n8.x4.shared.b16 "            \
        "{%0,%1,%2,%3}, [%4];"                                          \
        : "=r"((d)[0]), "=r"((d)[1]), "=r"((d)[2]), "=r"((d)[3])        \
        : "r"(addr))

#define LDSMX4T(d, addr)                                                \
    asm volatile("ldmatrix.sync.aligned.m8n8.x4.trans.shared.b16 "      \
        "{%0,%1,%2,%3}, [%4];"                                          \
        : "=r"((d)[0]), "=r"((d)[1]), "=r"((d)[2]), "=r"((d)[3])        \
        : "r"(addr))

#define CP_ASYNC16(sa, gp)                                              \
    asm volatile("cp.async.ca.shared.global [%0], [%1], 16;"            \
        :: "r"(sa), "l"(gp))
#define CP_COMMIT() asm volatile("cp.async.commit_group;")
#define CP_WAIT0()  asm volatile("cp.async.wait_group 0;")

__device__ __forceinline__ uint32_t packh2(float lo, float hi) {
    uint32_t r;
    asm("cvt.rn.f16x2.f32 %0, %1, %2;" : "=r"(r) : "f"(hi), "f"(lo));
    return r;
}
__device__ __forceinline__ uint32_t ex2h2(uint32_t x) {
    uint32_t r;
    asm("ex2.approx.f16x2 %0, %1;" : "=r"(r) : "r"(x));
    return r;
}
#define SM_SCALE_LOG2E 0.18033688011112042f   // 0.125 * log2(e)
#define ONES_H2 0x3C003C00u                   // half2(1.0, 1.0)

#define GS 72
#define AB (128 * GS * 2)            // A buffer: 128 rows x 64 halves (GS stride)
#define BB (64 * GS * 2)             // B buffer: 64 rows
#define GEMM_SMEM (2 * (AB + BB))    // 55296 bytes -> 4 CTAs/SM

extern __shared__ __align__(16) uint8_t dynsm[];

// ---- K0: transpose+convert x [b][c][n]->[b][n][c] f16, + weight conv --------
__global__ __launch_bounds__(256) void prep_kernel(const float* __restrict__ x,
                                                   const float* __restrict__ qw,
                                                   const float* __restrict__ kw,
                                                   const float* __restrict__ vw,
                                                   const float* __restrict__ pw) {
    __shared__ float t[32][33];
    const int flat = (blockIdx.z * 8 + blockIdx.y) * 72 + blockIdx.x;
    if (flat == 0) { g_sum[threadIdx.x] = 0.f; g_sumsq[threadIdx.x] = 0.f; }
    if (flat < 640) {
        int idx = flat * 256 + threadIdx.x;    // < 163840
        if (idx < 384 * CH) {
            int o = idx >> 8, c = idx & 255;
            float v;
            if (o < 256)      v = qw[o * CH + c];
            else if (o < 320) v = kw[(o - 256) * CH + c];
            else              v = vw[(o - 320) * CH + c];
            g_wqkv[idx] = __float2half(v);
        } else {
            int j = idx - 384 * CH;            // < 256*256
            g_pwh[j] = __float2half(pw[j]);
        }
    }

    const int n0 = blockIdx.x * 32;
    const int c0 = blockIdx.y * 32;
    const int b  = blockIdx.z;
    const int tx = threadIdx.x & 31, ty = threadIdx.x >> 5;
#pragma unroll
    for (int i = 0; i < 4; i++) {
        int cl = ty + i * 8;
        t[cl][tx] = x[((size_t)b * CH + c0 + cl) * NTOK + n0 + tx];
    }
    __syncthreads();
#pragma unroll
    for (int p = 0; p < 2; p++) {
        int w = threadIdx.x + p * 256;       // 512 items
        int nl = w >> 4, cp = w & 15;
        __half2 h = __floats2half2_rn(t[2 * cp][nl], t[2 * cp + 1][nl]);
        *(__half2*)&g_xh[((size_t)b * NTOK + n0 + nl) * CH + c0 + 2 * cp] = h;
    }
}

// ---------------- K1: QKV projection via HMMA, 128x64 tile, 4 CTA/SM ---------
// C[n][o] = sum_c xh[n][c] * wqkv[o][c].  grid (18 n-tiles of 128, 6 o, 8 b).
// 256 threads, 8 warps x 16 n-rows. cp.async double-buffered k-chunks of 64.
__global__ __launch_bounds__(256) void qkv_kernel() {
    const int bx = blockIdx.x, by = blockIdx.y, b = blockIdx.z;
    const int tid = threadIdx.x;
    const int w = tid >> 5, l = tid & 31;
    const int lr = l >> 2, c2 = (l & 3) * 2, t = l >> 3, rr = l & 7;
    const int q8 = tid & 7;

    const __half* Ag = g_xh + ((size_t)b * NTOK + bx * 128) * CH;
    const __half* Bg = g_wqkv + (size_t)by * 64 * CH;

    const uint32_t sm = smem_u32(dynsm);
    const uint32_t ldA0 = (uint32_t)((w * 16 + (t & 1) * 8 + rr) * GS + (t >> 1) * 8) * 2;
    const uint32_t ldB0 = (uint32_t)(((t >> 1) * 8 + rr) * GS + (t & 1) * 8) * 2;

    float acc[8][4];
#pragma unroll
    for (int nb = 0; nb < 8; nb++)
#pragma unroll
        for (int i = 0; i < 4; i++) acc[nb][i] = 0.f;

#pragma unroll
    for (int p = 0; p < 4; p++) {
        int row = (tid + p * 256) >> 3;
        CP_ASYNC16(sm + (uint32_t)(row * GS + q8 * 8) * 2,
                   Ag + (size_t)row * CH + q8 * 8);
    }
#pragma unroll
    for (int p = 0; p < 2; p++) {
        int row = (tid + p * 256) >> 3;
        CP_ASYNC16(sm + 2 * AB + (uint32_t)(row * GS + q8 * 8) * 2,
                   Bg + (size_t)row * CH + q8 * 8);
    }
    CP_COMMIT(); CP_WAIT0(); __syncthreads();

    for (int ck = 0; ck < 4; ck++) {
        const uint32_t abase = sm + (uint32_t)(ck & 1) * AB;
        const uint32_t bbase = sm + 2 * AB + (uint32_t)(ck & 1) * BB;
        if (ck < 3) {
            const int co = (ck + 1) * 64;
            const uint32_t a2 = sm + (uint32_t)((ck + 1) & 1) * AB;
            const uint32_t b2 = sm + 2 * AB + (uint32_t)((ck + 1) & 1) * BB;
#pragma unroll
            for (int p = 0; p < 4; p++) {
                int row = (tid + p * 256) >> 3;
                CP_ASYNC16(a2 + (uint32_t)(row * GS + q8 * 8) * 2,
                           Ag + (size_t)row * CH + co + q8 * 8);
            }
#pragma unroll
            for (int p = 0; p < 2; p++) {
                int row = (tid + p * 256) >> 3;
                CP_ASYNC16(b2 + (uint32_t)(row * GS + q8 * 8) * 2,
                           Bg + (size_t)row * CH + co + q8 * 8);
            }
            CP_COMMIT();
        }
#pragma unroll
        for (int ks = 0; ks < 4; ks++) {
            uint32_t aq[4];
            LDSMX4(aq, abase + ldA0 + (uint32_t)(ks * 16) * 2);
#pragma unroll
            for (int nbp = 0; nbp < 4; nbp++) {
                uint32_t bk[4];
                LDSMX4(bk, bbase + ldB0 + (uint32_t)(nbp * 16 * GS + ks * 16) * 2);
                MMA16816(acc[2 * nbp],     aq, (&bk[0]));
                MMA16816(acc[2 * nbp + 1], aq, (&bk[2]));
            }
        }
        if (ck < 3) CP_WAIT0();
        __syncthreads();
    }

    __half* base;
    float osc = 1.f;
    if (by < 4)       { base = g_qh + (size_t)(b * NHEADS + by) * NTOK * HDIM;
                        osc = SM_SCALE_LOG2E; }
    else if (by == 4)   base = g_kh + (size_t)b * NTOK * HDIM;
    else                base = g_vh + (size_t)b * NTOK * HDIM;
    const int n_r0 = bx * 128 + w * 16 + lr;
#pragma unroll
    for (int nb = 0; nb < 8; nb++) {
        int col = nb * 8 + c2;
        *(__half2*)&base[(size_t)n_r0 * HDIM + col] =
            __floats2half2_rn(acc[nb][0] * osc, acc[nb][1] * osc);
        *(__half2*)&base[(size_t)(n_r0 + 8) * HDIM + col] =
            __floats2half2_rn(acc[nb][2] * osc, acc[nb][3] * osc);
    }
}

// ---------------- K2: flash attention via HMMA, Bc-split pipelined -----------
// (round-12 version: Bc=64, half2 exp, ones-MMA row sums, cp.async dbl-buffer)
#define KVS 72
__global__ __launch_bounds__(128)
void attn_kernel() {
    __shared__ __half smK[2][64 * KVS];
    __shared__ __half smV[2][64 * KVS];

    const int n0  = blockIdx.x * 128;
    const int h   = blockIdx.y;
    const int b   = blockIdx.z;
    const int tid = threadIdx.x;
    const int w   = tid >> 5;
    const int l   = tid & 31;
    const int row0 = w * 32;

    const int lr  = l >> 2;
    const int c2  = (l & 3) * 2;
    const int t   = l >> 3;
    const int rr  = l & 7;

    const __half* qg = g_qh + ((size_t)(b * NHEADS + h) * NTOK + n0 + row0) * HDIM;
    uint32_t aq[2][4][4];
#pragma unroll
    for (int mi = 0; mi < 2; mi++)
#pragma unroll
        for (int ks = 0; ks < 4; ks++) {
            aq[mi][ks][0] = *(const uint32_t*)&qg[(mi * 16 + lr)     * HDIM + ks * 16 + c2];
            aq[mi][ks][1] = *(const uint32_t*)&qg[(mi * 16 + lr + 8) * HDIM + ks * 16 + c2];
            aq[mi][ks][2] = *(const uint32_t*)&qg[(mi * 16 + lr)     * HDIM + ks * 16 + c2 + 8];
            aq[mi][ks][3] = *(const uint32_t*)&qg[(mi * 16 + lr + 8) * HDIM + ks * 16 + c2 + 8];
        }

    const uint32_t smK_a = smem_u32(smK);
    const uint32_t smV_a = smem_u32(smV);
    const uint32_t bufB = (uint32_t)(64 * KVS * 2);
    const uint32_t ldK0 = smK_a + (uint32_t)(((t >> 1) * 8 + rr) * KVS + (t & 1) * 8) * 2;
    const uint32_t ldV0 = smV_a + (uint32_t)(((t & 1) * 8 + rr) * KVS + (t >> 1) * 8) * 2;

    const int q0 = tid & 7;
    const __half* kg = g_kh + (size_t)b * NTOK * HDIM;
    const __half* vg = g_vh + (size_t)b * NTOK * HDIM;

    float oacc[2][8][4];
#pragma unroll
    for (int mi = 0; mi < 2; mi++)
#pragma unroll
        for (int nb = 0; nb < 8; nb++)
#pragma unroll
            for (int i = 0; i < 4; i++) oacc[mi][nb][i] = 0.f;
    float lacc[2][4] = {{0.f, 0.f, 0.f, 0.f}, {0.f, 0.f, 0.f, 0.f}};
    const uint32_t ones[2] = {ONES_H2, ONES_H2};

#pragma unroll
    for (int p = 0; p < 4; p++) {
        int rl = (tid + p * 128) >> 3;
        uint32_t so = (uint32_t)(rl * KVS + q0 * 8) * 2;
        CP_ASYNC16(smK_a + so, kg + (size_t)rl * HDIM + q0 * 8);
        CP_ASYNC16(smV_a + so, vg + (size_t)rl * HDIM + q0 * 8);
    }
    CP_COMMIT();
    CP_WAIT0();
    __syncthreads();

    for (int it = 0; it < NKV; it++) {
        const uint32_t boff = (uint32_t)(it & 1) * bufB;

        if (it + 1 < NKV) {
            const int m1 = (it + 1) * 64;
            const uint32_t nb2 = (uint32_t)((it + 1) & 1) * bufB;
#pragma unroll
            for (int p = 0; p < 4; p++) {
                int rl = (tid + p * 128) >> 3;
                uint32_t so = nb2 + (uint32_t)(rl * KVS + q0 * 8) * 2;
                CP_ASYNC16(smK_a + so, kg + (size_t)(m1 + rl) * HDIM + q0 * 8);
                CP_ASYNC16(smV_a + so, vg + (size_t)(m1 + rl) * HDIM + q0 * 8);
            }
            CP_COMMIT();
        }

        uint32_t ap0[2][2][4], ap1[2][2][4];

        // ===== half A: j in [0,32) ===========================================
        {
            float sacc[2][4][4];
#pragma unroll
            for (int mi = 0; mi < 2; mi++)
#pragma unroll
                for (int nb = 0; nb < 4; nb++)
#pragma unroll
                    for (int i = 0; i < 4; i++) sacc[mi][nb][i] = 0.f;
#pragma unroll
            for (int ks = 0; ks < 4; ks++) {
                uint32_t bk0[4], bk1[4];
                LDSMX4(bk0, ldK0 + boff + (uint32_t)(0 * 16 * KVS + ks * 16) * 2);
                LDSMX4(bk1, ldK0 + boff + (uint32_t)(1 * 16 * KVS + ks * 16) * 2);
#pragma unroll
                for (int mi = 0; mi < 2; mi++) {
                    MMA16816(sacc[mi][0], aq[mi][ks], (&bk0[0]));
                    MMA16816(sacc[mi][1], aq[mi][ks], (&bk0[2]));
                    MMA16816(sacc[mi][2], aq[mi][ks], (&bk1[0]));
                    MMA16816(sacc[mi][3], aq[mi][ks], (&bk1[2]));
                }
            }
#pragma unroll
            for (int mi = 0; mi < 2; mi++)
#pragma unroll
                for (int kh = 0; kh < 2; kh++) {
                    ap0[mi][kh][0] = ex2h2(packh2(sacc[mi][2 * kh][0],     sacc[mi][2 * kh][1]));
                    ap0[mi][kh][1] = ex2h2(packh2(sacc[mi][2 * kh][2],     sacc[mi][2 * kh][3]));
                    ap0[mi][kh][2] = ex2h2(packh2(sacc[mi][2 * kh + 1][0], sacc[mi][2 * kh + 1][1]));
                    ap0[mi][kh][3] = ex2h2(packh2(sacc[mi][2 * kh + 1][2], sacc[mi][2 * kh + 1][3]));
                }
        }

        // ===== half B MMA1: j in [32,64) =====================================
        {
            float sacc[2][4][4];
#pragma unroll
            for (int mi = 0; mi < 2; mi++)
#pragma unroll
                for (int nb = 0; nb < 4; nb++)
#pragma unroll
                    for (int i = 0; i < 4; i++) sacc[mi][nb][i] = 0.f;
#pragma unroll
            for (int ks = 0; ks < 4; ks++) {
                uint32_t bk0[4], bk1[4];
                LDSMX4(bk0, ldK0 + boff + (uint32_t)(2 * 16 * KVS + ks * 16) * 2);
                LDSMX4(bk1, ldK0 + boff + (uint32_t)(3 * 16 * KVS + ks * 16) * 2);
#pragma unroll
                for (int mi = 0; mi < 2; mi++) {
                    MMA16816(sacc[mi][0], aq[mi][ks], (&bk0[0]));
                    MMA16816(sacc[mi][1], aq[mi][ks], (&bk0[2]));
                    MMA16816(sacc[mi][2], aq[mi][ks], (&bk1[0]));
                    MMA16816(sacc[mi][3], aq[mi][ks], (&bk1[2]));
                }
            }

#pragma unroll
            for (int kh = 0; kh < 2; kh++) {
                uint32_t bv[4][4];
#pragma unroll
                for (int nbp = 0; nbp < 4; nbp++)
                    LDSMX4T(bv[nbp], ldV0 + boff + (uint32_t)(kh * 16 * KVS + nbp * 16) * 2);
#pragma unroll
                for (int mi = 0; mi < 2; mi++) {
                    MMA16816(lacc[mi], ap0[mi][kh], ones);
#pragma unroll
                    for (int nbp = 0; nbp < 4; nbp++) {
                        MMA16816(oacc[mi][2 * nbp],     ap0[mi][kh], (&bv[nbp][0]));
                        MMA16816(oacc[mi][2 * nbp + 1], ap0[mi][kh], (&bv[nbp][2]));
                    }
                }
            }

#pragma unroll
            for (int mi = 0; mi < 2; mi++)
#pragma unroll
                for (int kh = 0; kh < 2; kh++) {
                    ap1[mi][kh][0] = ex2h2(packh2(sacc[mi][2 * kh][0],     sacc[mi][2 * kh][1]));
                    ap1[mi][kh][1] = ex2h2(packh2(sacc[mi][2 * kh][2],     sacc[mi][2 * kh][3]));
                    ap1[mi][kh][2] = ex2h2(packh2(sacc[mi][2 * kh + 1][0], sacc[mi][2 * kh + 1][1]));
                    ap1[mi][kh][3] = ex2h2(packh2(sacc[mi][2 * kh + 1][2], sacc[mi][2 * kh + 1][3]));
                }
        }

#pragma unroll
        for (int kh = 0; kh < 2; kh++) {
            uint32_t bv[4][4];
#pragma unroll
            for (int nbp = 0; nbp < 4; nbp++)
                LDSMX4T(bv[nbp], ldV0 + boff + (uint32_t)((kh + 2) * 16 * KVS + nbp * 16) * 2);
#pragma unroll
            for (int mi = 0; mi < 2; mi++) {
                MMA16816(lacc[mi], ap1[mi][kh], ones);
#pragma unroll
                for (int nbp = 0; nbp < 4; nbp++) {
                    MMA16816(oacc[mi][2 * nbp],     ap1[mi][kh], (&bv[nbp][0]));
                    MMA16816(oacc[mi][2 * nbp + 1], ap1[mi][kh], (&bv[nbp][2]));
                }
            }
        }

        if (it + 1 < NKV) CP_WAIT0();
        __syncthreads();
    }

    __half* ob = g_attnh + ((size_t)b * NTOK + n0 + row0) * HDTOT + h * HDIM;
#pragma unroll
    for (int mi = 0; mi < 2; mi++) {
        float inv0 = 1.f / lacc[mi][0];
        float inv1 = 1.f / lacc[mi][2];
#pragma unroll
        for (int nb = 0; nb < 8; nb++) {
            int col = nb * 8 + c2;
            *(__half2*)&ob[(size_t)(mi * 16 + lr)     * HDTOT + col] =
                __floats2half2_rn(oacc[mi][nb][0] * inv0, oacc[mi][nb][1] * inv0);
            *(__half2*)&ob[(size_t)(mi * 16 + lr + 8) * HDTOT + col] =
                __floats2half2_rn(oacc[mi][nb][2] * inv1, oacc[mi][nb][3] * inv1);
        }
    }
}

// ---------------- K3: output projection via HMMA, 128x64 tile, 4 CTA/SM -----
// C[c][n] = sum_o pwh[c][o] * attnh[n][o].  grid (36 n-tiles of 64, 2 c, 8 b).
__global__ __launch_bounds__(256) void proj_kernel(const float* __restrict__ pb) {
    const int bx = blockIdx.x, by = blockIdx.y, b = blockIdx.z;
    const int tid = threadIdx.x;
    const int w = tid >> 5, l = tid & 31;
    const int lr = l >> 2, c2 = (l & 3) * 2, t = l >> 3, rr = l & 7;
    const int q8 = tid & 7;

    const __half* Ag = g_pwh + (size_t)by * 128 * HDTOT;
    const __half* Bg = g_attnh + ((size_t)b * NTOK + bx * 64) * HDTOT;

    const uint32_t sm = smem_u32(dynsm);
    const uint32_t ldA0 = (uint32_t)((w * 16 + (t & 1) * 8 + rr) * GS + (t >> 1) * 8) * 2;
    const uint32_t ldB0 = (uint32_t)(((t >> 1) * 8 + rr) * GS + (t & 1) * 8) * 2;

    float acc[8][4];
#pragma unroll
    for (int nb = 0; nb < 8; nb++)
#pragma unroll
        for (int i = 0; i < 4; i++) acc[nb][i] = 0.f;

#pragma unroll
    for (int p = 0; p < 4; p++) {
        int row = (tid + p * 256) >> 3;
        CP_ASYNC16(sm + (uint32_t)(row * GS + q8 * 8) * 2,
                   Ag + (size_t)row * HDTOT + q8 * 8);
    }
#pragma unroll
    for (int p = 0; p < 2; p++) {
        int row = (tid + p * 256) >> 3;
        CP_ASYNC16(sm + 2 * AB + (uint32_t)(row * GS + q8 * 8) * 2,
                   Bg + (size_t)row * HDTOT + q8 * 8);
    }
    CP_COMMIT(); CP_WAIT0(); __syncthreads();

    for (int ck = 0; ck < 4; ck++) {
        const uint32_t abase = sm + (uint32_t)(ck & 1) * AB;
        const uint32_t bbase = sm + 2 * AB + (uint32_t)(ck & 1) * BB;
        if (ck < 3) {
            const int co = (ck + 1) * 64;
            const uint32_t a2 = sm + (uint32_t)((ck + 1) & 1) * AB;
            const uint32_t b2 = sm + 2 * AB + (uint32_t)((ck + 1) & 1) * BB;
#pragma unroll
            for (int p = 0; p < 4; p++) {
                int row = (tid + p * 256) >> 3;
                CP_ASYNC16(a2 + (uint32_t)(row * GS + q8 * 8) * 2,
                           Ag + (size_t)row * HDTOT + co + q8 * 8);
            }
#pragma unroll
            for (int p = 0; p < 2; p++) {
                int row = (tid + p * 256) >> 3;
                CP_ASYNC16(b2 + (uint32_t)(row * GS + q8 * 8) * 2,
                           Bg + (size_t)row * HDTOT + co + q8 * 8);
            }
            CP_COMMIT();
        }
#pragma unroll
        for (int ks = 0; ks < 4; ks++) {
            uint32_t aq[4];
            LDSMX4(aq, abase + ldA0 + (uint32_t)(ks * 16) * 2);
#pragma unroll
            for (int nbp = 0; nbp < 4; nbp++) {
                uint32_t bk[4];
                LDSMX4(bk, bbase + ldB0 + (uint32_t)(nbp * 16 * GS + ks * 16) * 2);
                MMA16816(acc[2 * nbp],     aq, (&bk[0]));
                MMA16816(acc[2 * nbp + 1], aq, (&bk[2]));
            }
        }
        if (ck < 3) CP_WAIT0();
        __syncthreads();
    }

    const int n0 = bx * 64;
    const int c_r0 = by * 128 + w * 16 + lr;
    const int c_r1 = c_r0 + 8;
    const float b0 = pb[c_r0], b1 = pb[c_r1];
    float s0 = 0.f, q0s = 0.f, s1 = 0.f, q1s = 0.f;
#pragma unroll
    for (int nb = 0; nb < 8; nb++) {
        int col = n0 + nb * 8 + c2;
        float v0 = acc[nb][0] + b0, v1 = acc[nb][1] + b0;
        float v2 = acc[nb][2] + b1, v3 = acc[nb][3] + b1;
        *(__half2*)&g_yh[((size_t)b * CH + c_r0) * NTOK + col] =
            __floats2half2_rn(v0, v1);
        *(__half2*)&g_yh[((size_t)b * CH + c_r1) * NTOK + col] =
            __floats2half2_rn(v2, v3);
        s0 += v0 + v1; q0s += v0 * v0 + v1 * v1;
        s1 += v2 + v3; q1s += v2 * v2 + v3 * v3;
    }
    s0 += __shfl_xor_sync(0xffffffffu, s0, 1);  s0 += __shfl_xor_sync(0xffffffffu, s0, 2);
    q0s += __shfl_xor_sync(0xffffffffu, q0s, 1); q0s += __shfl_xor_sync(0xffffffffu, q0s, 2);
    s1 += __shfl_xor_sync(0xffffffffu, s1, 1);  s1 += __shfl_xor_sync(0xffffffffu, s1, 2);
    q1s += __shfl_xor_sync(0xffffffffu, q1s, 1); q1s += __shfl_xor_sync(0xffffffffu, q1s, 2);
    if ((l & 3) == 0) {
        atomicAdd(&g_sum[c_r0], s0);  atomicAdd(&g_sumsq[c_r0], q0s);
        atomicAdd(&g_sum[c_r1], s1);  atomicAdd(&g_sumsq[c_r1], q1s);
    }
}

// ---------------- K4: BN finalize + residual (y in fp16) ---------------------
__global__ __launch_bounds__(192) void bn_kernel(const float* __restrict__ x,
                                                 const float* __restrict__ gamma,
                                                 const float* __restrict__ beta,
                                                 float* __restrict__ out) {
    const int i = blockIdx.x * 192 + threadIdx.x;   // float4 index; grid.x = 3
    const int c = blockIdx.y;
    const int b = blockIdx.z;
    const float invcnt = 1.f / (float)(BATCH * NTOK);
    float mean = g_sum[c] * invcnt;
    float var  = g_sumsq[c] * invcnt - mean * mean;
    float a = gamma[c] * rsqrtf(var + BN_EPS);
    float sh = beta[c] - a * mean;
    size_t i4 = (((size_t)b * CH + c) * NTOK) / 4 + i;
    __half2 y01 = ((const __half2*)g_yh)[i4 * 2];
    __half2 y23 = ((const __half2*)g_yh)[i4 * 2 + 1];
    float4 xr = ((const float4*)x)[i4];
    float2 f01 = __half22float2(y01);
    float2 f23 = __half22float2(y23);
    ((float4*)out)[i4] = make_float4(a * f01.x + sh + xr.x, a * f01.y + sh + xr.y,
                                     a * f23.x + sh + xr.z, a * f23.y + sh + xr.w);
}

// ---------------- launch ------------------------------------------------------
extern "C" void kernel_launch(void* const* d_in, const int* in_sizes, int n_in,
                              void* d_out, int out_size) {
    const float* x     = (const float*)d_in[0];
    const float* qw    = (const float*)d_in[1];
    const float* kw    = (const float*)d_in[2];
    const float* vw    = (const float*)d_in[3];
    const float* pw    = (const float*)d_in[4];
    const float* pb    = (const float*)d_in[5];
    const float* gamma = (const float*)d_in[6];
    const float* beta  = (const float*)d_in[7];
    float* out = (float*)d_out;

    cudaFuncSetAttribute(qkv_kernel, cudaFuncAttributeMaxDynamicSharedMemorySize,
                         GEMM_SMEM);
    cudaFuncSetAttribute(proj_kernel, cudaFuncAttributeMaxDynamicSharedMemorySize,
                         GEMM_SMEM);

    prep_kernel<<<dim3(NTOK / 32, CH / 32, BATCH), 256>>>(x, qw, kw, vw, pw);
    qkv_kernel<<<dim3(NTOK / 128, 6, BATCH), 256, GEMM_SMEM>>>();
    attn_kernel<<<dim3(NTOK / 128, NHEADS, BATCH), 128>>>();
    proj_kernel<<<dim3(NTOK / 64, 2, BATCH), 256, GEMM_SMEM>>>(pb);
    bn_kernel<<<dim3(NTOK / 768, CH, BATCH), 192>>>(x, gamma, beta, out);
}

// round 15
// speedup vs baseline: 1.0740x; 1.0273x over previous
#include <cuda_runtime.h>
#include <cuda_fp16.h>
#include <math.h>
#include <stdint.h>

#define BATCH    8
#define CH       256
#define NHEADS   4
#define HDIM     64
#define NTOK     2304          // 48*48
#define HDTOT    256
#define BN_EPS   1e-5f
#define NKV      (NTOK / 64)   // 36

// ---------------- scratch (static device globals; no allocation) ------------
__device__ __align__(16) __half g_xh[BATCH * NTOK * CH];            // [b][n][c]
__device__ __align__(16) __half g_wqkv[384 * CH];                   // [o][c]
__device__ __align__(16) __half g_pwh[CH * HDTOT];                  // [c][o]
__device__ __align__(16) __half g_qh[BATCH * NHEADS * NTOK * HDIM]; // [b][h][n][d]
__device__ __align__(16) __half g_kh[BATCH * NTOK * HDIM];          // [b][n][d]
__device__ __align__(16) __half g_vh[BATCH * NTOK * HDIM];          // [b][n][d]
__device__ __align__(16) __half g_attnh[BATCH * NTOK * HDTOT];      // [b][n][o]
__device__ __align__(16) __half g_yh[BATCH * CH * NTOK];            // [b][c][n] fp16
__device__ float g_sum[CH];
__device__ float g_sumsq[CH];

// ======================= PTX helpers =========================================
__device__ __forceinline__ uint32_t smem_u32(const void* p) {
    uint32_t a;
    asm("{ .reg .u64 t; cvta.to.shared.u64 t, %1; cvt.u32.u64 %0, t; }"
        : "=r"(a) : "l"(p));
    return a;
}

#define MMA16816(c, a, bf)                                              \
    asm volatile("mma.sync.aligned.m16n8k16.row.col.f32.f16.f16.f32 "   \
        "{%0,%1,%2,%3}, {%4,%5,%6,%7}, {%8,%9}, {%0,%1,%2,%3};"         \
        : "+f"((c)[0]), "+f"((c)[1]), "+f"((c)[2]), "+f"((c)[3])        \
        : "r"((a)[0]), "r"((a)[1]), "r"((a)[2]), "r"((a)[3]),           \
          "r"((bf)[0]), "r"((bf)[1]))

#define LDSMX4(d, addr)                                                 \
    asm volatile("ldmatrix.sync.aligned.m8n8.x4.shared.b16 "            \
        "{%0,%1,%2,%3}, [%4];"                                          \
        : "=r"((d)[0]), "=r"((d)[1]), "=r"((d)[2]), "=r"((d)[3])        \
        : "r"(addr))

#define LDSMX4T(d, addr)                                                \
    asm volatile("ldmatrix.sync.aligned.m8n8.x4.trans.shared.b16 "      \
        "{%0,%1,%2,%3}, [%4];"                                          \
        : "=r"((d)[0]), "=r"((d)[1]), "=r"((d)[2]), "=r"((d)[3])        \
        : "r"(addr))

#define CP_ASYNC16(sa, gp)                                              \
    asm volatile("cp.async.ca.shared.global [%0], [%1], 16;"            \
        :: "r"(sa), "l"(gp))
#define CP_ASYNC16CG(sa, gp)                                            \
    asm volatile("cp.async.cg.shared.global [%0], [%1], 16;"            \
        :: "r"(sa), "l"(gp))
#define CP_COMMIT() asm volatile("cp.async.commit_group;")
#define CP_WAIT0()  asm volatile("cp.async.wait_group 0;")

__device__ __forceinline__ uint32_t packh2(float lo, float hi) {
    uint32_t r;
    asm("cvt.rn.f16x2.f32 %0, %1, %2;" : "=r"(r) : "f"(hi), "f"(lo));
    return r;
}
__device__ __forceinline__ uint32_t ex2h2(uint32_t x) {
    uint32_t r;
    asm("ex2.approx.f16x2 %0, %1;" : "=r"(r) : "r"(x));
    return r;
}
#define SM_SCALE_LOG2E 0.18033688011112042f   // 0.125 * log2(e)
#define ONES_H2 0x3C003C00u                   // half2(1.0, 1.0)

#define GS 72
#define AB (256 * GS * 2)            // A buffer: 256 rows x 64 halves (GS stride)
#define BB (64 * GS * 2)             // B buffer: 64 rows
#define GEMM_SMEM (2 * (AB + BB))    // 92160 bytes

extern __shared__ __align__(16) uint8_t dynsm[];

// ---- K0: transpose+convert x [b][c][n]->[b][n][c] f16, + weight conv --------
// q-weights pre-scaled by 0.125*log2(e) so attention softmax is a bare exp2.
__global__ __launch_bounds__(256) void prep_kernel(const float* __restrict__ x,
                                                   const float* __restrict__ qw,
                                                   const float* __restrict__ kw,
                                                   const float* __restrict__ vw,
                                                   const float* __restrict__ pw) {
    __shared__ float t[32][33];
    const int flat = (blockIdx.z * 8 + blockIdx.y) * 72 + blockIdx.x;
    if (flat == 0) { g_sum[threadIdx.x] = 0.f; g_sumsq[threadIdx.x] = 0.f; }
    if (flat < 640) {
        int idx = flat * 256 + threadIdx.x;    // < 163840
        if (idx < 384 * CH) {
            int o = idx >> 8, c = idx & 255;
            float v;
            if (o < 256)      v = qw[o * CH + c] * SM_SCALE_LOG2E;
            else if (o < 320) v = kw[(o - 256) * CH + c];
            else              v = vw[(o - 320) * CH + c];
            g_wqkv[idx] = __float2half(v);
        } else {
            int j = idx - 384 * CH;            // < 256*256
            g_pwh[j] = __float2half(pw[j]);
        }
    }

    const int n0 = blockIdx.x * 32;
    const int c0 = blockIdx.y * 32;
    const int b  = blockIdx.z;
    const int tx = threadIdx.x & 31, ty = threadIdx.x >> 5;
#pragma unroll
    for (int i = 0; i < 4; i++) {
        int cl = ty + i * 8;
        t[cl][tx] = x[((size_t)b * CH + c0 + cl) * NTOK + n0 + tx];
    }
    __syncthreads();
#pragma unroll
    for (int p = 0; p < 2; p++) {
        int w = threadIdx.x + p * 256;       // 512 items
        int nl = w >> 4, cp = w & 15;
        __half2 h = __floats2half2_rn(t[2 * cp][nl], t[2 * cp + 1][nl]);
        *(__half2*)&g_xh[((size_t)b * NTOK + n0 + nl) * CH + c0 + 2 * cp] = h;
    }
}

// ---------------- K1: QKV projection via HMMA, wide tile ---------------------
// C[n][o] = sum_c xh[n][c] * wqkv[o][c].  grid (9 n-tiles of 256, 6 o, 8 b).
__global__ __launch_bounds__(256) void qkv_kernel() {
    const int bx = blockIdx.x, by = blockIdx.y, b = blockIdx.z;
    const int tid = threadIdx.x;
    const int w = tid >> 5, l = tid & 31;
    const int lr = l >> 2, c2 = (l & 3) * 2, t = l >> 3, rr = l & 7;
    const int q8 = tid & 7;

    const __half* Ag = g_xh + ((size_t)b * NTOK + bx * 256) * CH;
    const __half* Bg = g_wqkv + (size_t)by * 64 * CH;

    const uint32_t sm = smem_u32(dynsm);
    const uint32_t ldA0 = (uint32_t)((w * 32 + (t & 1) * 8 + rr) * GS + (t >> 1) * 8) * 2;
    const uint32_t ldB0 = (uint32_t)(((t >> 1) * 8 + rr) * GS + (t & 1) * 8) * 2;

    float acc[2][8][4];
#pragma unroll
    for (int mi = 0; mi < 2; mi++)
#pragma unroll
        for (int nb = 0; nb < 8; nb++)
#pragma unroll
            for (int i = 0; i < 4; i++) acc[mi][nb][i] = 0.f;

#pragma unroll
    for (int p = 0; p < 8; p++) {
        int row = (tid + p * 256) >> 3;
        CP_ASYNC16CG(sm + (uint32_t)(row * GS + q8 * 8) * 2,
                     Ag + (size_t)row * CH + q8 * 8);
    }
#pragma unroll
    for (int p = 0; p < 2; p++) {
        int row = (tid + p * 256) >> 3;
        CP_ASYNC16(sm + 2 * AB + (uint32_t)(row * GS + q8 * 8) * 2,
                   Bg + (size_t)row * CH + q8 * 8);
    }
    CP_COMMIT(); CP_WAIT0(); __syncthreads();

    for (int ck = 0; ck < 4; ck++) {
        const uint32_t abase = sm + (uint32_t)(ck & 1) * AB;
        const uint32_t bbase = sm + 2 * AB + (uint32_t)(ck & 1) * BB;
        if (ck < 3) {
            const int co = (ck + 1) * 64;
            const uint32_t a2 = sm + (uint32_t)((ck + 1) & 1) * AB;
            const uint32_t b2 = sm + 2 * AB + (uint32_t)((ck + 1) & 1) * BB;
#pragma unroll
            for (int p = 0; p < 8; p++) {
                int row = (tid + p * 256) >> 3;
                CP_ASYNC16CG(a2 + (uint32_t)(row * GS + q8 * 8) * 2,
                             Ag + (size_t)row * CH + co + q8 * 8);
            }
#pragma unroll
            for (int p = 0; p < 2; p++) {
                int row = (tid + p * 256) >> 3;
                CP_ASYNC16(b2 + (uint32_t)(row * GS + q8 * 8) * 2,
                           Bg + (size_t)row * CH + co + q8 * 8);
            }
            CP_COMMIT();
        }
#pragma unroll
        for (int ks = 0; ks < 4; ks++) {
            uint32_t aq0[4], aq1[4];
            LDSMX4(aq0, abase + ldA0 + (uint32_t)(ks * 16) * 2);
            LDSMX4(aq1, abase + ldA0 + (uint32_t)(16 * GS + ks * 16) * 2);
#pragma unroll
            for (int nbp = 0; nbp < 4; nbp++) {
                uint32_t bk[4];
                LDSMX4(bk, bbase + ldB0 + (uint32_t)(nbp * 16 * GS + ks * 16) * 2);
                MMA16816(acc[0][2 * nbp],     aq0, (&bk[0]));
                MMA16816(acc[0][2 * nbp + 1], aq0, (&bk[2]));
                MMA16816(acc[1][2 * nbp],     aq1, (&bk[0]));
                MMA16816(acc[1][2 * nbp + 1], aq1, (&bk[2]));
            }
        }
        if (ck < 3) CP_WAIT0();
        __syncthreads();
    }

    __half* base;
    if (by < 4)       base = g_qh + (size_t)(b * NHEADS + by) * NTOK * HDIM;
    else if (by == 4) base = g_kh + (size_t)b * NTOK * HDIM;
    else              base = g_vh + (size_t)b * NTOK * HDIM;
#pragma unroll
    for (int mi = 0; mi < 2; mi++) {
        const int n_r0 = bx * 256 + w * 32 + mi * 16 + lr;
#pragma unroll
        for (int nb = 0; nb < 8; nb++) {
            int col = nb * 8 + c2;
            *(__half2*)&base[(size_t)n_r0 * HDIM + col] =
                __floats2half2_rn(acc[mi][nb][0], acc[mi][nb][1]);
            *(__half2*)&base[(size_t)(n_r0 + 8) * HDIM + col] =
                __floats2half2_rn(acc[mi][nb][2], acc[mi][nb][3]);
        }
    }
}

// ---------------- K2: flash attention via HMMA, Bc-split pipelined -----------
// (round-12 version: Bc=64, half2 exp, ones-MMA row sums, cp.async dbl-buffer)
#define KVS 72
__global__ __launch_bounds__(128)
void attn_kernel() {
    __shared__ __half smK[2][64 * KVS];
    __shared__ __half smV[2][64 * KVS];

    const int n0  = blockIdx.x * 128;
    const int h   = blockIdx.y;
    const int b   = blockIdx.z;
    const int tid = threadIdx.x;
    const int w   = tid >> 5;
    const int l   = tid & 31;
    const int row0 = w * 32;

    const int lr  = l >> 2;
    const int c2  = (l & 3) * 2;
    const int t   = l >> 3;
    const int rr  = l & 7;

    const __half* qg = g_qh + ((size_t)(b * NHEADS + h) * NTOK + n0 + row0) * HDIM;
    uint32_t aq[2][4][4];
#pragma unroll
    for (int mi = 0; mi < 2; mi++)
#pragma unroll
        for (int ks = 0; ks < 4; ks++) {
            aq[mi][ks][0] = *(const uint32_t*)&qg[(mi * 16 + lr)     * HDIM + ks * 16 + c2];
            aq[mi][ks][1] = *(const uint32_t*)&qg[(mi * 16 + lr + 8) * HDIM + ks * 16 + c2];
            aq[mi][ks][2] = *(const uint32_t*)&qg[(mi * 16 + lr)     * HDIM + ks * 16 + c2 + 8];
            aq[mi][ks][3] = *(const uint32_t*)&qg[(mi * 16 + lr + 8) * HDIM + ks * 16 + c2 + 8];
        }

    const uint32_t smK_a = smem_u32(smK);
    const uint32_t smV_a = smem_u32(smV);
    const uint32_t bufB = (uint32_t)(64 * KVS * 2);
    const uint32_t ldK0 = smK_a + (uint32_t)(((t >> 1) * 8 + rr) * KVS + (t & 1) * 8) * 2;
    const uint32_t ldV0 = smV_a + (uint32_t)(((t & 1) * 8 + rr) * KVS + (t >> 1) * 8) * 2;

    const int q0 = tid & 7;
    const __half* kg = g_kh + (size_t)b * NTOK * HDIM;
    const __half* vg = g_vh + (size_t)b * NTOK * HDIM;

    float oacc[2][8][4];
#pragma unroll
    for (int mi = 0; mi < 2; mi++)
#pragma unroll
        for (int nb = 0; nb < 8; nb++)
#pragma unroll
            for (int i = 0; i < 4; i++) oacc[mi][nb][i] = 0.f;
    float lacc[2][4] = {{0.f, 0.f, 0.f, 0.f}, {0.f, 0.f, 0.f, 0.f}};
    const uint32_t ones[2] = {ONES_H2, ONES_H2};

#pragma unroll
    for (int p = 0; p < 4; p++) {
        int rl = (tid + p * 128) >> 3;
        uint32_t so = (uint32_t)(rl * KVS + q0 * 8) * 2;
        CP_ASYNC16(smK_a + so, kg + (size_t)rl * HDIM + q0 * 8);
        CP_ASYNC16(smV_a + so, vg + (size_t)rl * HDIM + q0 * 8);
    }
    CP_COMMIT();
    CP_WAIT0();
    __syncthreads();

    for (int it = 0; it < NKV; it++) {
        const uint32_t boff = (uint32_t)(it & 1) * bufB;

        if (it + 1 < NKV) {
            const int m1 = (it + 1) * 64;
            const uint32_t nb2 = (uint32_t)((it + 1) & 1) * bufB;
#pragma unroll
            for (int p = 0; p < 4; p++) {
                int rl = (tid + p * 128) >> 3;
                uint32_t so = nb2 + (uint32_t)(rl * KVS + q0 * 8) * 2;
                CP_ASYNC16(smK_a + so, kg + (size_t)(m1 + rl) * HDIM + q0 * 8);
                CP_ASYNC16(smV_a + so, vg + (size_t)(m1 + rl) * HDIM + q0 * 8);
            }
            CP_COMMIT();
        }

        uint32_t ap0[2][2][4], ap1[2][2][4];

        // ===== half A: j in [0,32) ===========================================
        {
            float sacc[2][4][4];
#pragma unroll
            for (int mi = 0; mi < 2; mi++)
#pragma unroll
                for (int nb = 0; nb < 4; nb++)
#pragma unroll
                    for (int i = 0; i < 4; i++) sacc[mi][nb][i] = 0.f;
#pragma unroll
            for (int ks = 0; ks < 4; ks++) {
                uint32_t bk0[4], bk1[4];
                LDSMX4(bk0, ldK0 + boff + (uint32_t)(0 * 16 * KVS + ks * 16) * 2);
                LDSMX4(bk1, ldK0 + boff + (uint32_t)(1 * 16 * KVS + ks * 16) * 2);
#pragma unroll
                for (int mi = 0; mi < 2; mi++) {
                    MMA16816(sacc[mi][0], aq[mi][ks], (&bk0[0]));
                    MMA16816(sacc[mi][1], aq[mi][ks], (&bk0[2]));
                    MMA16816(sacc[mi][2], aq[mi][ks], (&bk1[0]));
                    MMA16816(sacc[mi][3], aq[mi][ks], (&bk1[2]));
                }
            }
#pragma unroll
            for (int mi = 0; mi < 2; mi++)
#pragma unroll
                for (int kh = 0; kh < 2; kh++) {
                    ap0[mi][kh][0] = ex2h2(packh2(sacc[mi][2 * kh][0],     sacc[mi][2 * kh][1]));
                    ap0[mi][kh][1] = ex2h2(packh2(sacc[mi][2 * kh][2],     sacc[mi][2 * kh][3]));
                    ap0[mi][kh][2] = ex2h2(packh2(sacc[mi][2 * kh + 1][0], sacc[mi][2 * kh + 1][1]));
                    ap0[mi][kh][3] = ex2h2(packh2(sacc[mi][2 * kh + 1][2], sacc[mi][2 * kh + 1][3]));
                }
        }

        // ===== half B MMA1: j in [32,64) =====================================
        {
            float sacc[2][4][4];
#pragma unroll
            for (int mi = 0; mi < 2; mi++)
#pragma unroll
                for (int nb = 0; nb < 4; nb++)
#pragma unroll
                    for (int i = 0; i < 4; i++) sacc[mi][nb][i] = 0.f;
#pragma unroll
            for (int ks = 0; ks < 4; ks++) {
                uint32_t bk0[4], bk1[4];
                LDSMX4(bk0, ldK0 + boff + (uint32_t)(2 * 16 * KVS + ks * 16) * 2);
                LDSMX4(bk1, ldK0 + boff + (uint32_t)(3 * 16 * KVS + ks * 16) * 2);
#pragma unroll
                for (int mi = 0; mi < 2; mi++) {
                    MMA16816(sacc[mi][0], aq[mi][ks], (&bk0[0]));
                    MMA16816(sacc[mi][1], aq[mi][ks], (&bk0[2]));
                    MMA16816(sacc[mi][2], aq[mi][ks], (&bk1[0]));
                    MMA16816(sacc[mi][3], aq[mi][ks], (&bk1[2]));
                }
            }

#pragma unroll
            for (int kh = 0; kh < 2; kh++) {
                uint32_t bv[4][4];
#pragma unroll
                for (int nbp = 0; nbp < 4; nbp++)
                    LDSMX4T(bv[nbp], ldV0 + boff + (uint32_t)(kh * 16 * KVS + nbp * 16) * 2);
#pragma unroll
                for (int mi = 0; mi < 2; mi++) {
                    MMA16816(lacc[mi], ap0[mi][kh], ones);
#pragma unroll
                    for (int nbp = 0; nbp < 4; nbp++) {
                        MMA16816(oacc[mi][2 * nbp],     ap0[mi][kh], (&bv[nbp][0]));
                        MMA16816(oacc[mi][2 * nbp + 1], ap0[mi][kh], (&bv[nbp][2]));
                    }
                }
            }

#pragma unroll
            for (int mi = 0; mi < 2; mi++)
#pragma unroll
                for (int kh = 0; kh < 2; kh++) {
                    ap1[mi][kh][0] = ex2h2(packh2(sacc[mi][2 * kh][0],     sacc[mi][2 * kh][1]));
                    ap1[mi][kh][1] = ex2h2(packh2(sacc[mi][2 * kh][2],     sacc[mi][2 * kh][3]));
                    ap1[mi][kh][2] = ex2h2(packh2(sacc[mi][2 * kh + 1][0], sacc[mi][2 * kh + 1][1]));
                    ap1[mi][kh][3] = ex2h2(packh2(sacc[mi][2 * kh + 1][2], sacc[mi][2 * kh + 1][3]));
                }
        }

#pragma unroll
        for (int kh = 0; kh < 2; kh++) {
            uint32_t bv[4][4];
#pragma unroll
            for (int nbp = 0; nbp < 4; nbp++)
                LDSMX4T(bv[nbp], ldV0 + boff + (uint32_t)((kh + 2) * 16 * KVS + nbp * 16) * 2);
#pragma unroll
            for (int mi = 0; mi < 2; mi++) {
                MMA16816(lacc[mi], ap1[mi][kh], ones);
#pragma unroll
                for (int nbp = 0; nbp < 4; nbp++) {
                    MMA16816(oacc[mi][2 * nbp],     ap1[mi][kh], (&bv[nbp][0]));
                    MMA16816(oacc[mi][2 * nbp + 1], ap1[mi][kh], (&bv[nbp][2]));
                }
            }
        }

        if (it + 1 < NKV) CP_WAIT0();
        __syncthreads();
    }

    __half* ob = g_attnh + ((size_t)b * NTOK + n0 + row0) * HDTOT + h * HDIM;
#pragma unroll
    for (int mi = 0; mi < 2; mi++) {
        float inv0 = 1.f / lacc[mi][0];
        float inv1 = 1.f / lacc[mi][2];
#pragma unroll
        for (int nb = 0; nb < 8; nb++) {
            int col = nb * 8 + c2;
            *(__half2*)&ob[(size_t)(mi * 16 + lr)     * HDTOT + col] =
                __floats2half2_rn(oacc[mi][nb][0] * inv0, oacc[mi][nb][1] * inv0);
            *(__half2*)&ob[(size_t)(mi * 16 + lr + 8) * HDTOT + col] =
                __floats2half2_rn(oacc[mi][nb][2] * inv1, oacc[mi][nb][3] * inv1);
        }
    }
}

// ---------------- K3: output projection via HMMA, wide tile -----------------
__global__ __launch_bounds__(256) void proj_kernel(const float* __restrict__ pb) {
    const int bx = blockIdx.x, b = blockIdx.z;
    const int tid = threadIdx.x;
    const int w = tid >> 5, l = tid & 31;
    const int lr = l >> 2, c2 = (l & 3) * 2, t = l >> 3, rr = l & 7;
    const int q8 = tid & 7;

    const __half* Ag = g_pwh;
    const __half* Bg = g_attnh + ((size_t)b * NTOK + bx * 64) * HDTOT;

    const uint32_t sm = smem_u32(dynsm);
    const uint32_t ldA0 = (uint32_t)((w * 32 + (t & 1) * 8 + rr) * GS + (t >> 1) * 8) * 2;
    const uint32_t ldB0 = (uint32_t)(((t >> 1) * 8 + rr) * GS + (t & 1) * 8) * 2;

    float acc[2][8][4];
#pragma unroll
    for (int mi = 0; mi < 2; mi++)
#pragma unroll
        for (int nb = 0; nb < 8; nb++)
#pragma unroll
            for (int i = 0; i < 4; i++) acc[mi][nb][i] = 0.f;

#pragma unroll
    for (int p = 0; p < 8; p++) {
        int row = (tid + p * 256) >> 3;
        CP_ASYNC16(sm + (uint32_t)(row * GS + q8 * 8) * 2,
                   Ag + (size_t)row * HDTOT + q8 * 8);
    }
#pragma unroll
    for (int p = 0; p < 2; p++) {
        int row = (tid + p * 256) >> 3;
        CP_ASYNC16CG(sm + 2 * AB + (uint32_t)(row * GS + q8 * 8) * 2,
                     Bg + (size_t)row * HDTOT + q8 * 8);
    }
    CP_COMMIT(); CP_WAIT0(); __syncthreads();

    for (int ck = 0; ck < 4; ck++) {
        const uint32_t abase = sm + (uint32_t)(ck & 1) * AB;
        const uint32_t bbase = sm + 2 * AB + (uint32_t)(ck & 1) * BB;
        if (ck < 3) {
            const int co = (ck + 1) * 64;
            const uint32_t a2 = sm + (uint32_t)((ck + 1) & 1) * AB;
            const uint32_t b2 = sm + 2 * AB + (uint32_t)((ck + 1) & 1) * BB;
#pragma unroll
            for (int p = 0; p < 8; p++) {
                int row = (tid + p * 256) >> 3;
                CP_ASYNC16(a2 + (uint32_t)(row * GS + q8 * 8) * 2,
                           Ag + (size_t)row * HDTOT + co + q8 * 8);
            }
#pragma unroll
            for (int p = 0; p < 2; p++) {
                int row = (tid + p * 256) >> 3;
                CP_ASYNC16CG(b2 + (uint32_t)(row * GS + q8 * 8) * 2,
                             Bg + (size_t)row * HDTOT + co + q8 * 8);
            }
            CP_COMMIT();
        }
#pragma unroll
        for (int ks = 0; ks < 4; ks++) {
            uint32_t aq0[4], aq1[4];
            LDSMX4(aq0, abase + ldA0 + (uint32_t)(ks * 16) * 2);
            LDSMX4(aq1, abase + ldA0 + (uint32_t)(16 * GS + ks * 16) * 2);
#pragma unroll
            for (int nbp = 0; nbp < 4; nbp++) {
                uint32_t bk[4];
                LDSMX4(bk, bbase + ldB0 + (uint32_t)(nbp * 16 * GS + ks * 16) * 2);
                MMA16816(acc[0][2 * nbp],     aq0, (&bk[0]));
                MMA16816(acc[0][2 * nbp + 1], aq0, (&bk[2]));
                MMA16816(acc[1][2 * nbp],     aq1, (&bk[0]));
                MMA16816(acc[1][2 * nbp + 1], aq1, (&bk[2]));
            }
        }
        if (ck < 3) CP_WAIT0();
        __syncthreads();
    }

    const int n0 = bx * 64;
#pragma unroll
    for (int mi = 0; mi < 2; mi++) {
        const int c_r0 = w * 32 + mi * 16 + lr;
        const int c_r1 = c_r0 + 8;
        const float b0 = pb[c_r0], b1 = pb[c_r1];
        float s0 = 0.f, q0s = 0.f, s1 = 0.f, q1s = 0.f;
#pragma unroll
        for (int nb = 0; nb < 8; nb++) {
            int col = n0 + nb * 8 + c2;
            float v0 = acc[mi][nb][0] + b0, v1 = acc[mi][nb][1] + b0;
            float v2 = acc[mi][nb][2] + b1, v3 = acc[mi][nb][3] + b1;
            *(__half2*)&g_yh[((size_t)b * CH + c_r0) * NTOK + col] =
                __floats2half2_rn(v0, v1);
            *(__half2*)&g_yh[((size_t)b * CH + c_r1) * NTOK + col] =
                __floats2half2_rn(v2, v3);
            s0 += v0 + v1; q0s += v0 * v0 + v1 * v1;
            s1 += v2 + v3; q1s += v2 * v2 + v3 * v3;
        }
        s0 += __shfl_xor_sync(0xffffffffu, s0, 1);  s0 += __shfl_xor_sync(0xffffffffu, s0, 2);
        q0s += __shfl_xor_sync(0xffffffffu, q0s, 1); q0s += __shfl_xor_sync(0xffffffffu, q0s, 2);
        s1 += __shfl_xor_sync(0xffffffffu, s1, 1);  s1 += __shfl_xor_sync(0xffffffffu, s1, 2);
        q1s += __shfl_xor_sync(0xffffffffu, q1s, 1); q1s += __shfl_xor_sync(0xffffffffu, q1s, 2);
        if ((l & 3) == 0) {
            atomicAdd(&g_sum[c_r0], s0);  atomicAdd(&g_sumsq[c_r0], q0s);
            atomicAdd(&g_sum[c_r1], s1);  atomicAdd(&g_sumsq[c_r1], q1s);
        }
    }
}

// ---------------- K4: BN finalize + residual (y in fp16) ---------------------
__global__ __launch_bounds__(192) void bn_kernel(const float* __restrict__ x,
                                                 const float* __restrict__ gamma,
                                                 const float* __restrict__ beta,
                                                 float* __restrict__ out) {
    const int i = blockIdx.x * 192 + threadIdx.x;   // float4 index; grid.x = 3
    const int c = blockIdx.y;
    const int b = blockIdx.z;
    const float invcnt = 1.f / (float)(BATCH * NTOK);
    float mean = g_sum[c] * invcnt;
    float var  = g_sumsq[c] * invcnt - mean * mean;
    float a = gamma[c] * rsqrtf(var + BN_EPS);
    float sh = beta[c] - a * mean;
    size_t i4 = (((size_t)b * CH + c) * NTOK) / 4 + i;
    __half2 y01 = ((const __half2*)g_yh)[i4 * 2];
    __half2 y23 = ((const __half2*)g_yh)[i4 * 2 + 1];
    float4 xr = ((const float4*)x)[i4];
    float2 f01 = __half22float2(y01);
    float2 f23 = __half22float2(y23);
    ((float4*)out)[i4] = make_float4(a * f01.x + sh + xr.x, a * f01.y + sh + xr.y,
                                     a * f23.x + sh + xr.z, a * f23.y + sh + xr.w);
}

// ---------------- launch ------------------------------------------------------
extern "C" void kernel_launch(void* const* d_in, const int* in_sizes, int n_in,
                              void* d_out, int out_size) {
    const float* x     = (const float*)d_in[0];
    const float* qw    = (const float*)d_in[1];
    const float* kw    = (const float*)d_in[2];
    const float* vw    = (const float*)d_in[3];
    const float* pw    = (const float*)d_in[4];
    const float* pb    = (const float*)d_in[5];
    const float* gamma = (const float*)d_in[6];
    const float* beta  = (const float*)d_in[7];
    float* out = (float*)d_out;

    cudaFuncSetAttribute(qkv_kernel, cudaFuncAttributeMaxDynamicSharedMemorySize,
                         GEMM_SMEM);
    cudaFuncSetAttribute(proj_kernel, cudaFuncAttributeMaxDynamicSharedMemorySize,
                         GEMM_SMEM);

    prep_kernel<<<dim3(NTOK / 32, CH / 32, BATCH), 256>>>(x, qw, kw, vw, pw);
    qkv_kernel<<<dim3(NTOK / 256, 6, BATCH), 256, GEMM_SMEM>>>();
    attn_kernel<<<dim3(NTOK / 128, NHEADS, BATCH), 128>>>();
    proj_kernel<<<dim3(NTOK / 64, 1, BATCH), 256, GEMM_SMEM>>>(pb);
    bn_kernel<<<dim3(NTOK / 768, CH, BATCH), 192>>>(x, gamma, beta, out);
}